// round 7
// baseline (speedup 1.0000x reference)
#include <cuda_runtime.h>
#include <cstdint>

#define BB    64
#define HH    1024
#define SS    512
#define NTHR  64
#define NW    2
#define KK    16          // rows per thread (HH / NTHR)
#define TC    16          // t-steps per staged chunk
#define NCHUNK (SS / TC)  // 32
#define ROWB  80          // 64 B data (16 t-floats) + 16 B pad per row
#define STAGE_BYTES (HH * ROWB)
#define MASK_OFF    (2 * STAGE_BYTES)
#define RED_OFF     (MASK_OFF + SS * 4)
#define SMEM_TOTAL  (RED_OFF + 2 * NW * 4 * 4)

__device__ __forceinline__ float shfl_bfly(float v, int ofs) {
    unsigned r;
    asm volatile("shfl.sync.bfly.b32 %0, %1, %2, 0x1f, 0xffffffff;"
                 : "=r"(r) : "r"(__float_as_uint(v)), "r"(ofs));
    return __uint_as_float(r);
}

__device__ __forceinline__ void wred3(float& a, float& b, float& c) {
    #pragma unroll
    for (int ofs = 16; ofs > 0; ofs >>= 1) {
        a += shfl_bfly(a, ofs);
        b += shfl_bfly(b, ofs);
        c += shfl_bfly(c, ofs);
    }
}

__device__ __forceinline__ void cp16(uint32_t smem_dst, const void* gmem_src) {
    asm volatile("cp.async.cg.shared.global [%0], [%1], 16;"
                 :: "r"(smem_dst), "l"(gmem_src));
}

// Stage 8 of the 64 per-thread 16B slices of a chunk. piece in [0,8).
__device__ __forceinline__ void stage_piece(char* smem, const char* seq_b,
                                            int chunk, int piece, int tid) {
    char* dst_base = smem + (chunk & 1) * STAGE_BYTES;
    const char* src_base = seq_b + (size_t)chunk * (TC * 4);
    #pragma unroll
    for (int j = 0; j < 8; j++) {
        int idx = (piece * 8 + j) * NTHR + tid;   // 0..4095
        int row = idx >> 2;
        int p   = idx & 3;
        uint32_t d = (uint32_t)__cvta_generic_to_shared(dst_base + row * ROWB + p * 16);
        const char* s = src_base + (size_t)row * (SS * 4) + p * 16;
        cp16(d, s);
    }
    asm volatile("cp.async.commit_group;");
}

__global__ void __launch_bounds__(NTHR, 1)
orth_scan_kernel(const float* __restrict__ tree,
                 const float* __restrict__ seq,
                 const float* __restrict__ mask,
                 float* __restrict__ out)
{
    extern __shared__ char sm[];
    const int b    = blockIdx.x;
    const int tid  = threadIdx.x;
    const int wid  = tid >> 5;
    const int lane = tid & 31;

    const char* seq_b = (const char*)(seq + (size_t)b * HH * SS);
    float* msk = (float*)(sm + MASK_OFF);
    float* red = (float*)(sm + RED_OFF);

    #pragma unroll
    for (int i = tid; i < SS; i += NTHR) msk[i] = mask[b * SS + i];

    float h[KK], scur[KK];
    #pragma unroll
    for (int k = 0; k < KK; k++) h[k] = tree[b * HH + tid + k * NTHR];

    // Prologue: stage chunk 0, wait, load window group 0, init partials.
    #pragma unroll
    for (int p = 0; p < 8; p++) stage_piece(sm, seq_b, 0, p, tid);
    asm volatile("cp.async.wait_group 0;");
    __syncthreads();

    float4 s4[KK];                   // window: s for 4 consecutive t per row
    const uint32_t rowbase = tid * ROWB;

    float pdot, phh, pss;
    {
        float d0 = 0.f, d1 = 0.f, q0 = 0.f, q1 = 0.f, s0a = 0.f, s1a = 0.f;
        #pragma unroll
        for (int k = 0; k < KK; k++) {
            s4[k] = *(const float4*)(sm + rowbase + k * (NTHR * ROWB));
            float s0 = s4[k].x;
            scur[k] = s0;
            if (k & 1) { d1 = fmaf(h[k], s0, d1); q1 = fmaf(h[k], h[k], q1); s1a = fmaf(s0, s0, s1a); }
            else       { d0 = fmaf(h[k], s0, d0); q0 = fmaf(h[k], h[k], q0); s0a = fmaf(s0, s0, s0a); }
        }
        pdot = d0 + d1; phh = q0 + q1; pss = s0a + s1a;
    }

    for (int c = 0; c < NCHUNK; c++) {
        char* bufc = sm + (c & 1) * STAGE_BYTES;
        char* bufn = sm + ((c + 1) & 1) * STAGE_BYTES;
        const bool not_last = (c + 1) < NCHUNK;

        #pragma unroll
        for (int tl = 0; tl < TC; tl++) {
            const int t    = c * TC + tl;
            const int par  = tl & 1;
            const int comp = (tl + 1) & 3;          // component holding s_{t+1}

            // 1. Warp tree first (15 SHFLs).
            wred3(pdot, phh, pss);

            // 2. Pre-barrier independent work hides under tree:
            //    window refill from current buffer (valid all chunk).
            const float m = msk[t];
            if ((tl & 3) == 3 && tl != TC - 1) {
                const char* gb = bufc + (tl + 1) * 4;
                #pragma unroll
                for (int k = 0; k < KK; k++)
                    s4[k] = *(const float4*)(gb + rowbase + k * (NTHR * ROWB));
            }
            if (tl == TC - 1 && not_last)
                asm volatile("cp.async.wait_group 0;");

            // 3. Publish per-warp partials.
            if (lane == 0) {
                float4* rp = (float4*)(red + par * (NW * 4)) + wid;
                *rp = make_float4(pdot, phh, pss, 0.f);
            }
            __syncthreads();

            // 4. Chain-critical combine loads first (2 warps -> 2 slots)...
            const float4* rp = (const float4*)(red + par * (NW * 4));
            float4 v0 = rp[0], v1 = rp[1];

            // ...then boundary window refill from just-published buffer...
            if (tl == TC - 1) {
                #pragma unroll
                for (int k = 0; k < KK; k++)
                    s4[k] = *(const float4*)(bufn + rowbase + k * (NTHR * ROWB));
                // stale-but-in-bounds at t=511; results discarded
            }
            // ...then the staging burst for chunk c+1.
            if (tl < 8 && not_last)
                stage_piece(sm, seq_b, c + 1, tl, tid);

            // 5. Extract s_{t+1}; pss partial is h-independent.
            float sn[KK];
            #pragma unroll
            for (int k = 0; k < KK; k++)
                sn[k] = (comp == 0) ? s4[k].x : (comp == 1) ? s4[k].y
                      : (comp == 2) ? s4[k].z : s4[k].w;

            float s0a = 0.f, s1a = 0.f, s2a = 0.f, s3a = 0.f;
            #pragma unroll
            for (int k = 0; k < KK; k += 4) {
                s0a = fmaf(sn[k],     sn[k],     s0a);
                s1a = fmaf(sn[k + 1], sn[k + 1], s1a);
                s2a = fmaf(sn[k + 2], sn[k + 2], s2a);
                s3a = fmaf(sn[k + 3], sn[k + 3], s3a);
            }

            float dot = v0.x + v1.x;
            float hh  = v0.y + v1.y;
            float ss  = v0.z + v1.z;

            // cos = dot / max(||h||*||s||, 1e-8) == dot * rsqrt(max(hh*ss, 1e-16))
            const float cosv = dot * rsqrtf(fmaxf(hh * ss, 1e-16f));

            // 6. Update + fused next-step partials (4 accumulators each).
            float pd0 = 0.f, pd1 = 0.f, pd2 = 0.f, pd3 = 0.f;
            float ph0 = 0.f, ph1 = 0.f, ph2 = 0.f, ph3 = 0.f;
            #pragma unroll
            for (int k = 0; k < KK; k++) {
                float u  = fmaf(-cosv, h[k], scur[k]);   // s - h*cos
                float hn = fmaf(u, m, h[k]);             // h + u*m
                hn = fminf(1.0f, fmaxf(-1.0f, hn));      // clip
                switch (k & 3) {
                    case 0: pd0 = fmaf(hn, sn[k], pd0); ph0 = fmaf(hn, hn, ph0); break;
                    case 1: pd1 = fmaf(hn, sn[k], pd1); ph1 = fmaf(hn, hn, ph1); break;
                    case 2: pd2 = fmaf(hn, sn[k], pd2); ph2 = fmaf(hn, hn, ph2); break;
                    default: pd3 = fmaf(hn, sn[k], pd3); ph3 = fmaf(hn, hn, ph3); break;
                }
                h[k] = hn;
                scur[k] = sn[k];
            }
            pdot = (pd0 + pd1) + (pd2 + pd3);
            phh  = (ph0 + ph1) + (ph2 + ph3);
            pss  = (s0a + s1a) + (s2a + s3a);
        }
    }

    #pragma unroll
    for (int k = 0; k < KK; k++)
        out[b * HH + tid + k * NTHR] = h[k];
}

extern "C" void kernel_launch(void* const* d_in, const int* in_sizes, int n_in,
                              void* d_out, int out_size)
{
    const float* tree = (const float*)d_in[0];  // (B, H)
    const float* seq  = (const float*)d_in[1];  // (B, H, S)
    const float* mask = (const float*)d_in[2];  // (B, S)
    float* out = (float*)d_out;                 // (B, H)

    cudaFuncSetAttribute(orth_scan_kernel,
                         cudaFuncAttributeMaxDynamicSharedMemorySize, SMEM_TOTAL);
    orth_scan_kernel<<<BB, NTHR, SMEM_TOTAL>>>(tree, seq, mask, out);
}

// round 10
// speedup vs baseline: 1.1950x; 1.1950x over previous
#include <cuda_runtime.h>
#include <cstdint>

#define BB    64
#define HH    1024
#define SS    512
#define NTHR  128
#define NW    4
#define KK    8           // rows per thread
#define TC    16          // t-steps per staged chunk
#define NCHUNK (SS / TC)  // 32
#define ROWB  80          // 64 B data (16 t-floats) + 16 B pad per row
#define STAGE_BYTES (HH * ROWB)
#define MASK_OFF    (2 * STAGE_BYTES)
#define RED_OFF     (MASK_OFF + (SS + 4) * 4)
#define NSLOT       (NW * 2)                    // 2 writer lanes per warp
#define SMEM_TOTAL  (RED_OFF + 2 * NSLOT * 16)  // 2 parities * 8 slots * float4

__device__ __forceinline__ float shfl_bfly(float v, int ofs) {
    unsigned r;
    asm volatile("shfl.sync.bfly.b32 %0, %1, %2, 0x1f, 0xffffffff;"
                 : "=r"(r) : "r"(__float_as_uint(v)), "r"(ofs));
    return __uint_as_float(r);
}

// 4-level butterfly (offsets 16,8,4,2): afterwards lane 0 holds the even-lane
// sum, lane 1 the odd-lane sum (pairwise). Lanes 0,1 publish.
__device__ __forceinline__ void wred3_4(float& a, float& b, float& c) {
    #pragma unroll
    for (int ofs = 16; ofs > 1; ofs >>= 1) {
        a += shfl_bfly(a, ofs);
        b += shfl_bfly(b, ofs);
        c += shfl_bfly(c, ofs);
    }
}

__device__ __forceinline__ void cp16(uint32_t smem_dst, const void* gmem_src) {
    asm volatile("cp.async.cg.shared.global [%0], [%1], 16;"
                 :: "r"(smem_dst), "l"(gmem_src));
}

// Stage 4 of the 32 per-thread 16B slices of a chunk. piece in [0,8).
__device__ __forceinline__ void stage_piece(char* smem, const char* seq_b,
                                            int chunk, int piece, int tid) {
    char* dst_base = smem + (chunk & 1) * STAGE_BYTES;
    const char* src_base = seq_b + (size_t)chunk * (TC * 4);
    #pragma unroll
    for (int j = 0; j < 4; j++) {
        int idx = (piece * 4 + j) * NTHR + tid;
        int row = idx >> 2;
        int p   = idx & 3;
        uint32_t d = (uint32_t)__cvta_generic_to_shared(dst_base + row * ROWB + p * 16);
        const char* s = src_base + (size_t)row * (SS * 4) + p * 16;
        cp16(d, s);
    }
    asm volatile("cp.async.commit_group;");
}

__global__ void __launch_bounds__(NTHR, 1)
orth_scan_kernel(const float* __restrict__ tree,
                 const float* __restrict__ seq,
                 const float* __restrict__ mask,
                 float* __restrict__ out)
{
    extern __shared__ char sm[];
    const int b    = blockIdx.x;
    const int tid  = threadIdx.x;
    const int wid  = tid >> 5;
    const int lane = tid & 31;

    const char* seq_b = (const char*)(seq + (size_t)b * HH * SS);
    float* msk = (float*)(sm + MASK_OFF);
    float* red = (float*)(sm + RED_OFF);

    #pragma unroll
    for (int i = tid; i < SS; i += NTHR) msk[i] = mask[b * SS + i];
    if (tid == 0) msk[SS] = 0.f;   // prefetch guard

    float h[KK], scur[KK];
    #pragma unroll
    for (int k = 0; k < KK; k++) h[k] = tree[b * HH + tid + k * NTHR];

    #pragma unroll
    for (int p = 0; p < 8; p++) stage_piece(sm, seq_b, 0, p, tid);
    asm volatile("cp.async.wait_group 0;");
    __syncthreads();

    float4 s4[KK];
    const uint32_t rowbase = tid * ROWB;

    float pdot, phh, pss;
    {
        float d0 = 0.f, d1 = 0.f, q0 = 0.f, q1 = 0.f, s0a = 0.f, s1a = 0.f;
        #pragma unroll
        for (int k = 0; k < KK; k++) {
            s4[k] = *(const float4*)(sm + rowbase + k * (NTHR * ROWB));
            float s0 = s4[k].x;
            scur[k] = s0;
            if (k & 1) { d1 = fmaf(h[k], s0, d1); q1 = fmaf(h[k], h[k], q1); s1a = fmaf(s0, s0, s1a); }
            else       { d0 = fmaf(h[k], s0, d0); q0 = fmaf(h[k], h[k], q0); s0a = fmaf(s0, s0, s0a); }
        }
        pdot = d0 + d1; phh = q0 + q1; pss = s0a + s1a;
    }
    float mcur = msk[0];

    for (int c = 0; c < NCHUNK; c++) {
        char* bufc = sm + (c & 1) * STAGE_BYTES;
        char* bufn = sm + ((c + 1) & 1) * STAGE_BYTES;
        const bool not_last = (c + 1) < NCHUNK;

        #pragma unroll
        for (int tl = 0; tl < TC; tl++) {
            const int t    = c * TC + tl;
            const int par  = tl & 1;
            const int comp = (tl + 1) & 3;

            // 1. 4-level warp tree (12 SHFL).
            wred3_4(pdot, phh, pss);

            // 2. Publish: lanes 0,1 each write their half-warp partial.
            if (lane < 2) {
                float4* rp = (float4*)(red + par * (NSLOT * 4)) + (wid * 2 + lane);
                *rp = make_float4(pdot, phh, pss, 0.f);
            }

            // 3. Pre-barrier independent work (hides under tree + bar):
            //    mask prefetch, window refill, sn extraction, pss partial.
            const float m = mcur;
            mcur = msk[t + 1];

            float sn[KK];
            float pssn = 0.f;
            if (tl != TC - 1) {
                if ((tl & 3) == 3) {
                    const char* gb = bufc + (tl + 1) * 4;
                    #pragma unroll
                    for (int k = 0; k < KK; k++)
                        s4[k] = *(const float4*)(gb + rowbase + k * (NTHR * ROWB));
                }
                #pragma unroll
                for (int k = 0; k < KK; k++)
                    sn[k] = (comp == 0) ? s4[k].x : (comp == 1) ? s4[k].y
                          : (comp == 2) ? s4[k].z : s4[k].w;
                float a0 = 0.f, a1 = 0.f;
                #pragma unroll
                for (int k = 0; k < KK; k += 2) {
                    a0 = fmaf(sn[k],     sn[k],     a0);
                    a1 = fmaf(sn[k + 1], sn[k + 1], a1);
                }
                pssn = a0 + a1;
            } else if (not_last) {
                asm volatile("cp.async.wait_group 0;");
            }

            __syncthreads();

            // 4. Post-barrier: chain-critical combine loads first (8 slots).
            const float4* rp = (const float4*)(red + par * (NSLOT * 4));
            float4 v0 = rp[0], v1 = rp[1], v2 = rp[2], v3 = rp[3];
            float4 v4 = rp[4], v5 = rp[5], v6 = rp[6], v7 = rp[7];

            if (tl == TC - 1) {
                #pragma unroll
                for (int k = 0; k < KK; k++)
                    s4[k] = *(const float4*)(bufn + rowbase + k * (NTHR * ROWB));
                // stale-but-in-bounds at t=511; discarded
                #pragma unroll
                for (int k = 0; k < KK; k++)
                    sn[k] = (comp == 0) ? s4[k].x : (comp == 1) ? s4[k].y
                          : (comp == 2) ? s4[k].z : s4[k].w;
                float a0 = 0.f, a1 = 0.f;
                #pragma unroll
                for (int k = 0; k < KK; k += 2) {
                    a0 = fmaf(sn[k],     sn[k],     a0);
                    a1 = fmaf(sn[k + 1], sn[k + 1], a1);
                }
                pssn = a0 + a1;
            }
            if (tl < 8 && not_last)
                stage_piece(sm, seq_b, c + 1, tl, tid);

            float dot = ((v0.x + v1.x) + (v2.x + v3.x)) + ((v4.x + v5.x) + (v6.x + v7.x));
            float hh  = ((v0.y + v1.y) + (v2.y + v3.y)) + ((v4.y + v5.y) + (v6.y + v7.y));
            float ss  = ((v0.z + v1.z) + (v2.z + v3.z)) + ((v4.z + v5.z) + (v6.z + v7.z));

            // cos = dot / max(||h||*||s||, 1e-8) == dot * rsqrt(max(hh*ss, 1e-16))
            const float cosv = dot * rsqrtf(fmaxf(hh * ss, 1e-16f));

            // 5. Update + fused next-step partials.
            float pd0 = 0.f, pd1 = 0.f, pd2 = 0.f, pd3 = 0.f;
            float ph0 = 0.f, ph1 = 0.f, ph2 = 0.f, ph3 = 0.f;
            #pragma unroll
            for (int k = 0; k < KK; k++) {
                float u  = fmaf(-cosv, h[k], scur[k]);   // s - h*cos
                float hn = fmaf(u, m, h[k]);             // h + u*m
                hn = fminf(1.0f, fmaxf(-1.0f, hn));      // clip
                switch (k & 3) {
                    case 0: pd0 = fmaf(hn, sn[k], pd0); ph0 = fmaf(hn, hn, ph0); break;
                    case 1: pd1 = fmaf(hn, sn[k], pd1); ph1 = fmaf(hn, hn, ph1); break;
                    case 2: pd2 = fmaf(hn, sn[k], pd2); ph2 = fmaf(hn, hn, ph2); break;
                    default: pd3 = fmaf(hn, sn[k], pd3); ph3 = fmaf(hn, hn, ph3); break;
                }
                h[k] = hn;
                scur[k] = sn[k];
            }
            pdot = (pd0 + pd1) + (pd2 + pd3);
            phh  = (ph0 + ph1) + (ph2 + ph3);
            pss  = pssn;
        }
    }

    #pragma unroll
    for (int k = 0; k < KK; k++)
        out[b * HH + tid + k * NTHR] = h[k];
}

extern "C" void kernel_launch(void* const* d_in, const int* in_sizes, int n_in,
                              void* d_out, int out_size)
{
    const float* tree = (const float*)d_in[0];  // (B, H)
    const float* seq  = (const float*)d_in[1];  // (B, H, S)
    const float* mask = (const float*)d_in[2];  // (B, S)
    float* out = (float*)d_out;                 // (B, H)

    cudaFuncSetAttribute(orth_scan_kernel,
                         cudaFuncAttributeMaxDynamicSharedMemorySize, SMEM_TOTAL);
    orth_scan_kernel<<<BB, NTHR, SMEM_TOTAL>>>(tree, seq, mask, out);
}

// round 12
// speedup vs baseline: 1.2467x; 1.0433x over previous
#include <cuda_runtime.h>
#include <cstdint>

#define BB    64
#define HH    1024
#define SS    512
#define NTHR  128
#define NW    4
#define KK    8           // rows per thread
#define NP    4           // packed row-pairs per thread
#define TC    16          // t-steps per staged chunk
#define NCHUNK (SS / TC)  // 32
#define ROWB  80          // 64 B data (16 t-floats) + 16 B pad per row
#define STAGE_BYTES (HH * ROWB)
#define MASK_OFF    (2 * STAGE_BYTES)
#define RED_OFF     (MASK_OFF + (SS + 4) * 4)
#define SMEM_TOTAL  (RED_OFF + 2 * NW * 16)   // 2 parities * 4 warps * float4

typedef unsigned long long u64;

// ---- packed f32x2 helpers (sm_103a: only fma/mul/add exist packed) ----
__device__ __forceinline__ u64 pack2(float lo, float hi) {
    u64 r; asm("mov.b64 %0, {%1, %2};" : "=l"(r) : "f"(lo), "f"(hi)); return r;
}
__device__ __forceinline__ void unpack2(u64 v, float& lo, float& hi) {
    asm("mov.b64 {%0, %1}, %2;" : "=f"(lo), "=f"(hi) : "l"(v));
}
__device__ __forceinline__ u64 fma2(u64 a, u64 b, u64 c) {
    u64 d; asm("fma.rn.f32x2 %0, %1, %2, %3;" : "=l"(d) : "l"(a), "l"(b), "l"(c)); return d;
}
__device__ __forceinline__ u64 mul2(u64 a, u64 b) {
    u64 d; asm("mul.rn.f32x2 %0, %1, %2;" : "=l"(d) : "l"(a), "l"(b)); return d;
}
__device__ __forceinline__ u64 add2(u64 a, u64 b) {
    u64 d; asm("add.rn.f32x2 %0, %1, %2;" : "=l"(d) : "l"(a), "l"(b)); return d;
}
// Clamp to [-1,1]: unpack -> scalar FMNMX (alu pipe, overlaps fma pipe) -> repack.
// The pack/unpack movs are register-pair splits that ptxas folds away.
__device__ __forceinline__ u64 clip2(u64 v) {
    float lo, hi; unpack2(v, lo, hi);
    lo = fminf(1.0f, fmaxf(-1.0f, lo));
    hi = fminf(1.0f, fmaxf(-1.0f, hi));
    return pack2(lo, hi);
}
__device__ __forceinline__ float hsum2_2(u64 a, u64 b) {  // sum of 4 floats
    u64 e = add2(a, b);
    float lo, hi; unpack2(e, lo, hi); return lo + hi;
}

__device__ __forceinline__ float shfl_bfly(float v, int ofs) {
    unsigned r;
    asm volatile("shfl.sync.bfly.b32 %0, %1, %2, 0x1f, 0xffffffff;"
                 : "=r"(r) : "r"(__float_as_uint(v)), "r"(ofs));
    return __uint_as_float(r);
}

// Full 5-level butterfly; three independent chains pipeline.
__device__ __forceinline__ void wred3(float& a, float& b, float& c) {
    #pragma unroll
    for (int ofs = 16; ofs > 0; ofs >>= 1) {
        a += shfl_bfly(a, ofs);
        b += shfl_bfly(b, ofs);
        c += shfl_bfly(c, ofs);
    }
}

__device__ __forceinline__ void cp16(uint32_t smem_dst, const void* gmem_src) {
    asm volatile("cp.async.cg.shared.global [%0], [%1], 16;"
                 :: "r"(smem_dst), "l"(gmem_src));
}

// Stage 4 of the 32 per-thread 16B slices of a chunk. piece in [0,8).
__device__ __forceinline__ void stage_piece(char* smem, const char* seq_b,
                                            int chunk, int piece, int tid) {
    char* dst_base = smem + (chunk & 1) * STAGE_BYTES;
    const char* src_base = seq_b + (size_t)chunk * (TC * 4);
    #pragma unroll
    for (int j = 0; j < 4; j++) {
        int idx = (piece * 4 + j) * NTHR + tid;
        int row = idx >> 2;
        int p   = idx & 3;
        uint32_t d = (uint32_t)__cvta_generic_to_shared(dst_base + row * ROWB + p * 16);
        const char* s = src_base + (size_t)row * (SS * 4) + p * 16;
        cp16(d, s);
    }
    asm volatile("cp.async.commit_group;");
}

__global__ void __launch_bounds__(NTHR, 1)
orth_scan_kernel(const float* __restrict__ tree,
                 const float* __restrict__ seq,
                 const float* __restrict__ mask,
                 float* __restrict__ out)
{
    extern __shared__ char sm[];
    const int b    = blockIdx.x;
    const int tid  = threadIdx.x;
    const int wid  = tid >> 5;
    const int lane = tid & 31;

    const char* seq_b = (const char*)(seq + (size_t)b * HH * SS);
    float* msk = (float*)(sm + MASK_OFF);
    float* red = (float*)(sm + RED_OFF);

    #pragma unroll
    for (int i = tid; i < SS; i += NTHR) msk[i] = mask[b * SS + i];
    if (tid == 0) msk[SS] = 0.f;   // prefetch guard

    // Carried state, packed by row pairs: pair j = rows (tid+2j*128, tid+(2j+1)*128)
    u64 h2[NP], scur2[NP];
    {
        float hv[KK];
        #pragma unroll
        for (int k = 0; k < KK; k++) hv[k] = tree[b * HH + tid + k * NTHR];
        #pragma unroll
        for (int j = 0; j < NP; j++) h2[j] = pack2(hv[2 * j], hv[2 * j + 1]);
    }

    #pragma unroll
    for (int p = 0; p < 8; p++) stage_piece(sm, seq_b, 0, p, tid);
    asm volatile("cp.async.wait_group 0;");
    __syncthreads();

    float4 s4[KK];
    const uint32_t rowbase = tid * ROWB;

    float pdot, phh, pss;
    {
        #pragma unroll
        for (int k = 0; k < KK; k++)
            s4[k] = *(const float4*)(sm + rowbase + k * (NTHR * ROWB));
        #pragma unroll
        for (int j = 0; j < NP; j++) scur2[j] = pack2(s4[2 * j].x, s4[2 * j + 1].x);
        u64 d0 = 0, d1 = 0, q0 = 0, q1 = 0, w0 = 0, w1 = 0;
        #pragma unroll
        for (int j = 0; j < NP; j++) {
            u64* dd = (j & 1) ? &d1 : &d0;
            u64* qq = (j & 1) ? &q1 : &q0;
            u64* ww = (j & 1) ? &w1 : &w0;
            *dd = fma2(h2[j], scur2[j], *dd);
            *qq = fma2(h2[j], h2[j], *qq);
            *ww = fma2(scur2[j], scur2[j], *ww);
        }
        pdot = hsum2_2(d0, d1); phh = hsum2_2(q0, q1); pss = hsum2_2(w0, w1);
    }
    float mcur = msk[0];

    for (int c = 0; c < NCHUNK; c++) {
        char* bufc = sm + (c & 1) * STAGE_BYTES;
        char* bufn = sm + ((c + 1) & 1) * STAGE_BYTES;
        const bool not_last = (c + 1) < NCHUNK;

        #pragma unroll
        for (int tl = 0; tl < TC; tl++) {
            const int t    = c * TC + tl;
            const int par  = tl & 1;
            const int comp = (tl + 1) & 3;

            // 1. 5-level warp tree (15 SHFL), issues first.
            wred3(pdot, phh, pss);

            // 2. Publish per-warp partials (lane 0).
            if (lane == 0) {
                float4* rp = (float4*)(red + par * (NW * 4)) + wid;
                *rp = make_float4(pdot, phh, pss, 0.f);
            }

            // 3. Pre-barrier cos-independent work (hides under tree + bar):
            //    mask, bs = m*scur, window refill, sn pack, pss partial.
            const float m = mcur;
            mcur = msk[t + 1];
            const u64 m2 = pack2(m, m);

            u64 bs2[NP];
            #pragma unroll
            for (int j = 0; j < NP; j++) bs2[j] = mul2(m2, scur2[j]);

            u64 sn2[NP];
            float pssn = 0.f;
            if (tl != TC - 1) {
                if ((tl & 3) == 3) {
                    const char* gb = bufc + (tl + 1) * 4;
                    #pragma unroll
                    for (int k = 0; k < KK; k++)
                        s4[k] = *(const float4*)(gb + rowbase + k * (NTHR * ROWB));
                }
                #pragma unroll
                for (int j = 0; j < NP; j++) {
                    float a = (comp == 0) ? s4[2*j].x : (comp == 1) ? s4[2*j].y
                            : (comp == 2) ? s4[2*j].z : s4[2*j].w;
                    float bb = (comp == 0) ? s4[2*j+1].x : (comp == 1) ? s4[2*j+1].y
                             : (comp == 2) ? s4[2*j+1].z : s4[2*j+1].w;
                    sn2[j] = pack2(a, bb);
                }
                u64 w0 = 0, w1 = 0;
                #pragma unroll
                for (int j = 0; j < NP; j++) {
                    if (j & 1) w1 = fma2(sn2[j], sn2[j], w1);
                    else       w0 = fma2(sn2[j], sn2[j], w0);
                }
                pssn = hsum2_2(w0, w1);
            } else if (not_last) {
                asm volatile("cp.async.wait_group 0;");
            }

            __syncthreads();

            // 4. Post-barrier: chain-critical combine loads first (4 slots).
            const float4* rp = (const float4*)(red + par * (NW * 4));
            float4 v0 = rp[0], v1 = rp[1], v2 = rp[2], v3 = rp[3];

            if (tl == TC - 1) {
                #pragma unroll
                for (int k = 0; k < KK; k++)
                    s4[k] = *(const float4*)(bufn + rowbase + k * (NTHR * ROWB));
                // stale-but-in-bounds at t=511; results discarded
                #pragma unroll
                for (int j = 0; j < NP; j++) {
                    float a = (comp == 0) ? s4[2*j].x : (comp == 1) ? s4[2*j].y
                            : (comp == 2) ? s4[2*j].z : s4[2*j].w;
                    float bb = (comp == 0) ? s4[2*j+1].x : (comp == 1) ? s4[2*j+1].y
                             : (comp == 2) ? s4[2*j+1].z : s4[2*j+1].w;
                    sn2[j] = pack2(a, bb);
                }
                u64 w0 = 0, w1 = 0;
                #pragma unroll
                for (int j = 0; j < NP; j++) {
                    if (j & 1) w1 = fma2(sn2[j], sn2[j], w1);
                    else       w0 = fma2(sn2[j], sn2[j], w0);
                }
                pssn = hsum2_2(w0, w1);
            }
            if (tl < 8 && not_last)
                stage_piece(sm, seq_b, c + 1, tl, tid);

            float dot = (v0.x + v1.x) + (v2.x + v3.x);
            float hh  = (v0.y + v1.y) + (v2.y + v3.y);
            float ss  = (v0.z + v1.z) + (v2.z + v3.z);

            // cos = dot / max(||h||*||s||, 1e-8) == dot * rsqrt(max(hh*ss, 1e-16))
            const float cosv = dot * rsqrtf(fmaxf(hh * ss, 1e-16f));

            // 5. Update: h_new = clip(alpha*h + m*s), alpha = 1 - m*cos.
            //    (m in {0,1}: exact for m=0; fp32-noise association for m=1.)
            const float alpha = fmaf(-m, cosv, 1.0f);
            const u64 a2 = pack2(alpha, alpha);

            u64 pd0 = 0, pd1 = 0, ph0 = 0, ph1 = 0;
            #pragma unroll
            for (int j = 0; j < NP; j++) {
                u64 hn = fma2(a2, h2[j], bs2[j]);
                hn = clip2(hn);
                if (j & 1) { pd1 = fma2(hn, sn2[j], pd1); ph1 = fma2(hn, hn, ph1); }
                else       { pd0 = fma2(hn, sn2[j], pd0); ph0 = fma2(hn, hn, ph0); }
                h2[j]    = hn;
                scur2[j] = sn2[j];
            }
            pdot = hsum2_2(pd0, pd1);
            phh  = hsum2_2(ph0, ph1);
            pss  = pssn;
        }
    }

    #pragma unroll
    for (int j = 0; j < NP; j++) {
        float lo, hi; unpack2(h2[j], lo, hi);
        out[b * HH + tid + (2 * j) * NTHR]     = lo;
        out[b * HH + tid + (2 * j + 1) * NTHR] = hi;
    }
}

extern "C" void kernel_launch(void* const* d_in, const int* in_sizes, int n_in,
                              void* d_out, int out_size)
{
    const float* tree = (const float*)d_in[0];  // (B, H)
    const float* seq  = (const float*)d_in[1];  // (B, H, S)
    const float* mask = (const float*)d_in[2];  // (B, S)
    float* out = (float*)d_out;                 // (B, H)

    cudaFuncSetAttribute(orth_scan_kernel,
                         cudaFuncAttributeMaxDynamicSharedMemorySize, SMEM_TOTAL);
    orth_scan_kernel<<<BB, NTHR, SMEM_TOTAL>>>(tree, seq, mask, out);
}